// round 3
// baseline (speedup 1.0000x reference)
#include <cuda_runtime.h>
#include <math.h>

#define N_NODES 50000
#define N_EDGES 800000
#define IN_C    64
#define HID     128
#define OUT_C   2
#define N_GRAPHS 64

// ---------------- scratch (static device globals; allowed per harness rules) ----
__device__ float g_deg [N_NODES];
__device__ float g_dinv[N_NODES];
__device__ float g_norm[N_EDGES];
__device__ float g_agg [N_NODES * HID];   // aggregation buffer (64 or 128 feats)
__device__ float g_h   [N_NODES * HID];   // hidden node features
__device__ float g_pool[N_GRAPHS * HID];
__device__ float g_cnt [N_GRAPHS];
__device__ float g_gh  [N_GRAPHS * HID];

// ---------------- helpers ----------------
__device__ __forceinline__ void red_add_v4(float* p, float4 v) {
    asm volatile("red.global.add.v4.f32 [%0], {%1,%2,%3,%4};"
                 :: "l"(p), "f"(v.x), "f"(v.y), "f"(v.z), "f"(v.w) : "memory");
}

// ---------------- degree / norm ----------------
__global__ void k_deg_init() {
    int i = blockIdx.x * blockDim.x + threadIdx.x;
    if (i < N_NODES) g_deg[i] = 1.0f;          // self loop
}
__global__ void k_deg_acc(const int* __restrict__ dst) {
    int e = blockIdx.x * blockDim.x + threadIdx.x;
    if (e < N_EDGES) atomicAdd(&g_deg[dst[e]], 1.0f);
}
__global__ void k_dinv() {
    int i = blockIdx.x * blockDim.x + threadIdx.x;
    if (i < N_NODES) g_dinv[i] = rsqrtf(g_deg[i]);
}
__global__ void k_norm(const int* __restrict__ src,
                       const int* __restrict__ dst) {
    int e = blockIdx.x * blockDim.x + threadIdx.x;
    if (e < N_EDGES) g_norm[e] = g_dinv[src[e]] * g_dinv[dst[e]];
}

// ---------------- aggregation layer 1 (feat = x, 64 feats = 16 float4) -------
__global__ void k_self_init1(const float4* __restrict__ feat) {
    int i = blockIdx.x * blockDim.x + threadIdx.x;
    if (i >= N_NODES * 16) return;
    int n = i >> 4;
    float d = g_dinv[n];
    float s = d * d;
    float4 v = feat[i];
    v.x *= s; v.y *= s; v.z *= s; v.w *= s;
    ((float4*)g_agg)[i] = v;
}
__global__ void k_edge1(const int* __restrict__ src,
                        const int* __restrict__ dst,
                        const float4* __restrict__ feat) {
    int idx = blockIdx.x * blockDim.x + threadIdx.x;
    if (idx >= N_EDGES * 16) return;
    int e = idx >> 4;
    int c = idx & 15;
    float nrm = g_norm[e];
    int s = src[e];
    int d = dst[e];
    float4 v = feat[(size_t)s * 16 + c];
    v.x *= nrm; v.y *= nrm; v.z *= nrm; v.w *= nrm;
    red_add_v4(g_agg + (size_t)d * 64 + c * 4, v);
}

// ---------------- aggregation layer 2 (feat = g_h, 128 feats = 32 float4) ----
__global__ void k_self_init2() {
    int i = blockIdx.x * blockDim.x + threadIdx.x;
    if (i >= N_NODES * 32) return;
    int n = i >> 5;
    float d = g_dinv[n];
    float s = d * d;
    float4 v = ((const float4*)g_h)[i];
    v.x *= s; v.y *= s; v.z *= s; v.w *= s;
    ((float4*)g_agg)[i] = v;
}
__global__ void k_edge2(const int* __restrict__ src,
                        const int* __restrict__ dst) {
    int idx = blockIdx.x * blockDim.x + threadIdx.x;
    if (idx >= N_EDGES * 32) return;
    int e = idx >> 5;
    int c = idx & 31;
    float nrm = g_norm[e];
    int s = src[e];
    int d = dst[e];
    float4 v = ((const float4*)g_h)[(size_t)s * 32 + c];
    v.x *= nrm; v.y *= nrm; v.z *= nrm; v.w *= nrm;
    red_add_v4(g_agg + (size_t)d * 128 + c * 4, v);
}

// ---------------- GEMM: g_h[N,128] = g_agg[N,K] @ W[K,128] + b (opt relu) ----
// block: 32 rows x 128 cols, 256 threads. K tiled by 64 -> static smem 40 KB.
template<int K, bool RELU>
__global__ void __launch_bounds__(256) k_gemm(const float* __restrict__ W,
                                              const float* __restrict__ b) {
    __shared__ __align__(16) float sW[64 * 128];   // 32 KB
    __shared__ __align__(16) float sA[32 * 64];    //  8 KB
    int tx = threadIdx.x & 31;
    int ty = threadIdx.x >> 5;
    int row0 = blockIdx.x * 32;

    float acc[4][4];
    #pragma unroll
    for (int rr = 0; rr < 4; rr++)
        #pragma unroll
        for (int cc = 0; cc < 4; cc++) acc[rr][cc] = 0.f;

    const float4* W4 = (const float4*)W;
    const float4* A4 = (const float4*)g_agg;
    const int KQ = K / 4;

    for (int kt = 0; kt < K; kt += 64) {
        for (int i = threadIdx.x; i < 64 * 32; i += 256)
            ((float4*)sW)[i] = W4[kt * 32 + i];
        for (int i = threadIdx.x; i < 32 * 16; i += 256) {
            int r = i >> 4;
            int c = i & 15;
            int gr = row0 + r;
            float4 v = (gr < N_NODES) ? A4[(size_t)gr * KQ + (kt >> 2) + c]
                                      : make_float4(0.f, 0.f, 0.f, 0.f);
            ((float4*)sA)[i] = v;
        }
        __syncthreads();

        #pragma unroll 8
        for (int k = 0; k < 64; k++) {
            float4 w = ((float4*)sW)[k * 32 + tx];
            #pragma unroll
            for (int rr = 0; rr < 4; rr++) {
                float a = sA[(ty * 4 + rr) * 64 + k];
                acc[rr][0] += a * w.x;
                acc[rr][1] += a * w.y;
                acc[rr][2] += a * w.z;
                acc[rr][3] += a * w.w;
            }
        }
        __syncthreads();
    }

    float4 bb = ((const float4*)b)[tx];
    #pragma unroll
    for (int rr = 0; rr < 4; rr++) {
        int gr = row0 + ty * 4 + rr;
        if (gr < N_NODES) {
            float4 o;
            o.x = acc[rr][0] + bb.x;
            o.y = acc[rr][1] + bb.y;
            o.z = acc[rr][2] + bb.z;
            o.w = acc[rr][3] + bb.w;
            if (RELU) {
                o.x = fmaxf(o.x, 0.f); o.y = fmaxf(o.y, 0.f);
                o.z = fmaxf(o.z, 0.f); o.w = fmaxf(o.w, 0.f);
            }
            ((float4*)g_h)[(size_t)gr * 32 + tx] = o;
        }
    }
}

// ---------------- pooling ----------------
__global__ void k_pool_zero() {
    int i = blockIdx.x * blockDim.x + threadIdx.x;
    if (i < N_GRAPHS * HID) g_pool[i] = 0.f;
    if (i < N_GRAPHS) g_cnt[i] = 0.f;
}
__global__ void k_cnt(const int* __restrict__ batch) {
    int n = blockIdx.x * blockDim.x + threadIdx.x;
    if (n < N_NODES) atomicAdd(&g_cnt[batch[n]], 1.0f);
}
// run-length smem accumulation (batch sorted); 128 threads = HID cols, 256 nodes/block
__global__ void __launch_bounds__(128) k_pool(const int* __restrict__ batch) {
    __shared__ int sb[256];
    int n0 = blockIdx.x * 256;
    int n1 = min(n0 + 256, N_NODES);
    for (int i = threadIdx.x; i < n1 - n0; i += 128) sb[i] = batch[n0 + i];
    __syncthreads();
    int j = threadIdx.x;
    int cur = sb[0];
    float acc = 0.f;
    for (int n = n0; n < n1; n++) {
        int b = sb[n - n0];
        if (b != cur) {
            atomicAdd(&g_pool[cur * HID + j], acc);
            cur = b; acc = 0.f;
        }
        acc += g_h[(size_t)n * HID + j];
    }
    atomicAdd(&g_pool[cur * HID + j], acc);
}

// ---------------- MLP head ----------------
__global__ void __launch_bounds__(128) k_mlp1(const float* __restrict__ Wm1,
                                              const float* __restrict__ bm1) {
    __shared__ float grow[HID];
    int r = blockIdx.x;
    int j = threadIdx.x;
    grow[j] = g_pool[r * HID + j] / fmaxf(g_cnt[r], 1.0f);
    __syncthreads();
    float acc = bm1[j];
    #pragma unroll 8
    for (int k = 0; k < HID; k++) acc += grow[k] * Wm1[k * HID + j];
    g_gh[r * HID + j] = fmaxf(acc, 0.f);
}
__global__ void __launch_bounds__(128) k_mlp2(const float* __restrict__ Wm2,
                                              const float* __restrict__ bm2,
                                              float* __restrict__ out) {
    int tid = threadIdx.x;           // 128 = 64 graphs * 2 outs
    int r = tid >> 1;
    int o = tid & 1;
    float acc = bm2[o];
    #pragma unroll 8
    for (int k = 0; k < HID; k++) acc += g_gh[r * HID + k] * Wm2[k * OUT_C + o];
    out[r * OUT_C + o] = acc;
}

// ---------------- launch ----------------
static inline int cdiv(int a, int b) { return (a + b - 1) / b; }

extern "C" void kernel_launch(void* const* d_in, const int* in_sizes, int n_in,
                              void* d_out, int out_size) {
    const float* x    = (const float*)d_in[0];
    const int*   ei   = (const int*)d_in[1];     // int32 (JAX x64 disabled)
    const int*   src  = ei;
    const int*   dst  = ei + N_EDGES;
    const int*   batch= (const int*)d_in[2];     // int32
    const float* W1  = (const float*)d_in[3];
    const float* b1  = (const float*)d_in[4];
    const float* W2  = (const float*)d_in[5];
    const float* b2  = (const float*)d_in[6];
    const float* Wm1 = (const float*)d_in[7];
    const float* bm1 = (const float*)d_in[8];
    const float* Wm2 = (const float*)d_in[9];
    const float* bm2 = (const float*)d_in[10];
    float* out = (float*)d_out;

    const int T = 256;

    // degree + normalization
    k_deg_init<<<cdiv(N_NODES, T), T>>>();
    k_deg_acc <<<cdiv(N_EDGES, T), T>>>(dst);
    k_dinv    <<<cdiv(N_NODES, T), T>>>();
    k_norm    <<<cdiv(N_EDGES, T), T>>>(src, dst);

    // layer 1: aggregate x (64 feats) then transform  ((A*X)*W halves scatter traffic)
    k_self_init1<<<cdiv(N_NODES * 16, T), T>>>((const float4*)x);
    k_edge1     <<<cdiv(N_EDGES * 16, T), T>>>(src, dst, (const float4*)x);
    k_gemm<64, true><<<cdiv(N_NODES, 32), 256>>>(W1, b1);

    // layer 2: aggregate h (128 feats) then transform
    k_self_init2<<<cdiv(N_NODES * 32, T), T>>>();
    k_edge2     <<<cdiv(N_EDGES * 32, T), T>>>(src, dst);
    k_gemm<128, false><<<cdiv(N_NODES, 32), 256>>>(W2, b2);

    // mean pool + MLP head
    k_pool_zero<<<cdiv(N_GRAPHS * HID, T), T>>>();
    k_cnt      <<<cdiv(N_NODES, T), T>>>(batch);
    k_pool     <<<cdiv(N_NODES, 256), 128>>>(batch);
    k_mlp1     <<<N_GRAPHS, HID>>>(Wm1, bm1);
    k_mlp2     <<<1, N_GRAPHS * OUT_C>>>(Wm2, bm2, out);
}

// round 4
// speedup vs baseline: 1.2723x; 1.2723x over previous
#include <cuda_runtime.h>
#include <math.h>

#define N_NODES 50000
#define N_EDGES 800000
#define IN_C    64
#define HID     128
#define OUT_C   2
#define N_GRAPHS 64

// ---------------- scratch (static device globals) ----------------
__device__ int   g_cnt_e [N_NODES];        // in-degree (edges only)
__device__ float g_dinv  [N_NODES];
__device__ int   g_off   [N_NODES + 1];    // CSR offsets
__device__ int   g_cursor[N_NODES];        // CSR fill cursors
__device__ int   g_csr   [N_EDGES];        // src node per CSR slot
__device__ float g_agg   [N_NODES * HID];
__device__ float g_h     [N_NODES * HID];
__device__ float g_pool  [N_GRAPHS * HID];
__device__ float g_gcnt  [N_GRAPHS];

// ---------------- zero + degree ----------------
__global__ void k_zero() {
    int i = blockIdx.x * blockDim.x + threadIdx.x;
    if (i < N_NODES) g_cnt_e[i] = 0;
    if (i < N_GRAPHS * HID) g_pool[i] = 0.f;
    if (i < N_GRAPHS) g_gcnt[i] = 0.f;
}
__global__ void k_deg_acc(const int* __restrict__ dst) {
    int e = blockIdx.x * blockDim.x + threadIdx.x;
    if (e < N_EDGES) atomicAdd(&g_cnt_e[dst[e]], 1);
}

// ---------------- single-block exclusive scan (+dinv) ----------------
__global__ void __launch_bounds__(1024) k_scan() {
    __shared__ int wsum[32];
    __shared__ int s_carry;
    int t = threadIdx.x, lane = t & 31, w = t >> 5;
    if (t == 0) s_carry = 0;
    __syncthreads();
    for (int base = 0; base < N_NODES; base += 1024) {
        int i = base + t;
        int v = (i < N_NODES) ? g_cnt_e[i] : 0;
        int x = v;
        #pragma unroll
        for (int d = 1; d < 32; d <<= 1) {
            int y = __shfl_up_sync(0xffffffffu, x, d);
            if (lane >= d) x += y;
        }
        if (lane == 31) wsum[w] = x;
        __syncthreads();
        if (w == 0) {
            int y = wsum[lane];
            #pragma unroll
            for (int d = 1; d < 32; d <<= 1) {
                int z = __shfl_up_sync(0xffffffffu, y, d);
                if (lane >= d) y += z;
            }
            wsum[lane] = y;
        }
        __syncthreads();
        int excl = s_carry + (w ? wsum[w - 1] : 0) + x - v;
        if (i < N_NODES) {
            g_off[i]    = excl;
            g_cursor[i] = excl;
            g_dinv[i]   = rsqrtf((float)v + 1.0f);
        }
        __syncthreads();
        if (t == 0) s_carry += wsum[31];
        __syncthreads();
    }
    if (t == 0) g_off[N_NODES] = N_EDGES;
}

// ---------------- CSR build ----------------
__global__ void k_csr(const int* __restrict__ src, const int* __restrict__ dst) {
    int e = blockIdx.x * blockDim.x + threadIdx.x;
    if (e >= N_EDGES) return;
    int d = dst[e];
    int pos = atomicAdd(&g_cursor[d], 1);
    g_csr[pos] = src[e];
}

// ---------------- aggregation layer 1 (x: 64 feats = 16 float4) --------------
// warp per node; lanes 0-15 even edges, 16-31 odd edges, butterfly combine.
__global__ void __launch_bounds__(256) k_agg1(const float4* __restrict__ X) {
    int warp = (blockIdx.x * blockDim.x + threadIdx.x) >> 5;
    if (warp >= N_NODES) return;
    int lane = threadIdx.x & 31;
    int c    = lane & 15;
    int half = lane >> 4;
    int n = warp;
    float dn = g_dinv[n];
    float4 acc = make_float4(0.f, 0.f, 0.f, 0.f);
    if (half == 0) {                    // self term counted once
        float4 v = X[(size_t)n * 16 + c];
        acc.x = dn * v.x; acc.y = dn * v.y; acc.z = dn * v.z; acc.w = dn * v.w;
    }
    int e0 = g_off[n] + half, e1 = g_off[n + 1];
    for (int e = e0; e < e1; e += 2) {
        int s = g_csr[e];
        float ds = g_dinv[s];
        float4 v = X[(size_t)s * 16 + c];
        acc.x += ds * v.x; acc.y += ds * v.y; acc.z += ds * v.z; acc.w += ds * v.w;
    }
    acc.x += __shfl_xor_sync(0xffffffffu, acc.x, 16);
    acc.y += __shfl_xor_sync(0xffffffffu, acc.y, 16);
    acc.z += __shfl_xor_sync(0xffffffffu, acc.z, 16);
    acc.w += __shfl_xor_sync(0xffffffffu, acc.w, 16);
    if (half == 0) {
        acc.x *= dn; acc.y *= dn; acc.z *= dn; acc.w *= dn;
        ((float4*)g_agg)[(size_t)n * 16 + c] = acc;
    }
}

// ---------------- aggregation layer 2 (g_h: 128 feats = 32 float4) -----------
__global__ void __launch_bounds__(256) k_agg2() {
    int warp = (blockIdx.x * blockDim.x + threadIdx.x) >> 5;
    if (warp >= N_NODES) return;
    int lane = threadIdx.x & 31;
    int n = warp;
    float dn = g_dinv[n];
    const float4* H = (const float4*)g_h;
    float4 v = H[(size_t)n * 32 + lane];
    float4 acc;
    acc.x = dn * v.x; acc.y = dn * v.y; acc.z = dn * v.z; acc.w = dn * v.w;
    int e0 = g_off[n], e1 = g_off[n + 1];
    int e = e0;
    for (; e + 1 < e1; e += 2) {
        int s0 = g_csr[e], s1 = g_csr[e + 1];
        float d0 = g_dinv[s0], d1 = g_dinv[s1];
        float4 v0 = H[(size_t)s0 * 32 + lane];
        float4 v1 = H[(size_t)s1 * 32 + lane];
        acc.x += d0 * v0.x + d1 * v1.x;
        acc.y += d0 * v0.y + d1 * v1.y;
        acc.z += d0 * v0.z + d1 * v1.z;
        acc.w += d0 * v0.w + d1 * v1.w;
    }
    if (e < e1) {
        int s0 = g_csr[e];
        float d0 = g_dinv[s0];
        float4 v0 = H[(size_t)s0 * 32 + lane];
        acc.x += d0 * v0.x; acc.y += d0 * v0.y; acc.z += d0 * v0.z; acc.w += d0 * v0.w;
    }
    acc.x *= dn; acc.y *= dn; acc.z *= dn; acc.w *= dn;
    ((float4*)g_agg)[(size_t)n * 32 + lane] = acc;
}

// ---------------- GEMM: g_h[N,128] = g_agg[N,K] @ W[K,128] + b (opt relu) ----
// 64-row x 128-col tile, 256 threads, 8x4 outputs/thread, all-float4 LDS.
template<int K, bool RELU>
__global__ void __launch_bounds__(256) k_gemm(const float* __restrict__ W,
                                              const float* __restrict__ b) {
    __shared__ __align__(16) float sW[64 * 128];   // 32 KB (K-tile 64)
    __shared__ __align__(16) float sA[64 * 64];    // 16 KB
    int tx = threadIdx.x & 31;       // col group (4 cols)
    int ty = threadIdx.x >> 5;       // row base (rows ty, ty+8, ..., ty+56)
    int row0 = blockIdx.x * 64;

    float acc[8][4];
    #pragma unroll
    for (int rr = 0; rr < 8; rr++)
        #pragma unroll
        for (int cc = 0; cc < 4; cc++) acc[rr][cc] = 0.f;

    const float4* W4 = (const float4*)W;
    const float4* A4 = (const float4*)g_agg;
    const int KQ = K / 4;

    for (int kt = 0; kt < K; kt += 64) {
        for (int i = threadIdx.x; i < 64 * 32; i += 256)
            ((float4*)sW)[i] = W4[kt * 32 + i];
        for (int i = threadIdx.x; i < 64 * 16; i += 256) {
            int r = i >> 4;
            int c = i & 15;
            int gr = row0 + r;
            float4 v = (gr < N_NODES) ? A4[(size_t)gr * KQ + (kt >> 2) + c]
                                      : make_float4(0.f, 0.f, 0.f, 0.f);
            ((float4*)sA)[i] = v;
        }
        __syncthreads();

        #pragma unroll
        for (int k4 = 0; k4 < 16; k4++) {
            float4 w0 = ((float4*)sW)[(k4 * 4 + 0) * 32 + tx];
            float4 w1 = ((float4*)sW)[(k4 * 4 + 1) * 32 + tx];
            float4 w2 = ((float4*)sW)[(k4 * 4 + 2) * 32 + tx];
            float4 w3 = ((float4*)sW)[(k4 * 4 + 3) * 32 + tx];
            #pragma unroll
            for (int rr = 0; rr < 8; rr++) {
                float4 a = ((float4*)sA)[(ty + rr * 8) * 16 + k4];
                acc[rr][0] += a.x * w0.x + a.y * w1.x + a.z * w2.x + a.w * w3.x;
                acc[rr][1] += a.x * w0.y + a.y * w1.y + a.z * w2.y + a.w * w3.y;
                acc[rr][2] += a.x * w0.z + a.y * w1.z + a.z * w2.z + a.w * w3.z;
                acc[rr][3] += a.x * w0.w + a.y * w1.w + a.z * w2.w + a.w * w3.w;
            }
        }
        __syncthreads();
    }

    float4 bb = ((const float4*)b)[tx];
    #pragma unroll
    for (int rr = 0; rr < 8; rr++) {
        int gr = row0 + ty + rr * 8;
        if (gr < N_NODES) {
            float4 o;
            o.x = acc[rr][0] + bb.x;
            o.y = acc[rr][1] + bb.y;
            o.z = acc[rr][2] + bb.z;
            o.w = acc[rr][3] + bb.w;
            if (RELU) {
                o.x = fmaxf(o.x, 0.f); o.y = fmaxf(o.y, 0.f);
                o.z = fmaxf(o.z, 0.f); o.w = fmaxf(o.w, 0.f);
            }
            ((float4*)g_h)[(size_t)gr * 32 + tx] = o;
        }
    }
}

// ---------------- pooling (batch sorted; run-length, counts fused) -----------
__global__ void __launch_bounds__(128) k_pool(const int* __restrict__ batch) {
    __shared__ int sb[256];
    int n0 = blockIdx.x * 256;
    int n1 = min(n0 + 256, N_NODES);
    for (int i = threadIdx.x; i < n1 - n0; i += 128) sb[i] = batch[n0 + i];
    __syncthreads();
    int j = threadIdx.x;
    int cur = sb[0];
    int segstart = n0;
    float acc = 0.f;
    for (int n = n0; n < n1; n++) {
        int b = sb[n - n0];
        if (b != cur) {
            atomicAdd(&g_pool[cur * HID + j], acc);
            if (j == 0) atomicAdd(&g_gcnt[cur], (float)(n - segstart));
            cur = b; acc = 0.f; segstart = n;
        }
        acc += g_h[(size_t)n * HID + j];
    }
    atomicAdd(&g_pool[cur * HID + j], acc);
    if (j == 0) atomicAdd(&g_gcnt[cur], (float)(n1 - segstart));
}

// ---------------- fused MLP head ----------------
__global__ void __launch_bounds__(128) k_mlp(const float* __restrict__ Wm1,
                                             const float* __restrict__ bm1,
                                             const float* __restrict__ Wm2,
                                             const float* __restrict__ bm2,
                                             float* __restrict__ out) {
    __shared__ float grow[HID];
    __shared__ float r0[HID], r1[HID];
    int r = blockIdx.x;
    int j = threadIdx.x;
    grow[j] = g_pool[r * HID + j] / fmaxf(g_gcnt[r], 1.0f);
    __syncthreads();
    float acc = bm1[j];
    #pragma unroll 8
    for (int k = 0; k < HID; k++) acc += grow[k] * Wm1[k * HID + j];
    float h = fmaxf(acc, 0.f);
    r0[j] = h * Wm2[j * OUT_C + 0];
    r1[j] = h * Wm2[j * OUT_C + 1];
    __syncthreads();
    #pragma unroll
    for (int s = 64; s > 0; s >>= 1) {
        if (j < s) { r0[j] += r0[j + s]; r1[j] += r1[j + s]; }
        __syncthreads();
    }
    if (j == 0) {
        out[r * OUT_C + 0] = r0[0] + bm2[0];
        out[r * OUT_C + 1] = r1[0] + bm2[1];
    }
}

// ---------------- launch ----------------
static inline int cdiv(int a, int b) { return (a + b - 1) / b; }

extern "C" void kernel_launch(void* const* d_in, const int* in_sizes, int n_in,
                              void* d_out, int out_size) {
    const float* x    = (const float*)d_in[0];
    const int*   ei   = (const int*)d_in[1];     // int32
    const int*   src  = ei;
    const int*   dst  = ei + N_EDGES;
    const int*   batch= (const int*)d_in[2];     // int32
    const float* W1  = (const float*)d_in[3];
    const float* b1  = (const float*)d_in[4];
    const float* W2  = (const float*)d_in[5];
    const float* b2  = (const float*)d_in[6];
    const float* Wm1 = (const float*)d_in[7];
    const float* bm1 = (const float*)d_in[8];
    const float* Wm2 = (const float*)d_in[9];
    const float* bm2 = (const float*)d_in[10];
    float* out = (float*)d_out;

    const int T = 256;

    // CSR build: degree -> scan -> bucket scatter
    k_zero   <<<cdiv(N_NODES, T), T>>>();
    k_deg_acc<<<cdiv(N_EDGES, T), T>>>(dst);
    k_scan   <<<1, 1024>>>();
    k_csr    <<<cdiv(N_EDGES, T), T>>>(src, dst);

    // layer 1: gather-aggregate x (64 feats), then transform + relu
    k_agg1<<<cdiv(N_NODES * 32, T), T>>>((const float4*)x);
    k_gemm<64, true><<<cdiv(N_NODES, 64), 256>>>(W1, b1);

    // layer 2: gather-aggregate h (128 feats), then transform
    k_agg2<<<cdiv(N_NODES * 32, T), T>>>();
    k_gemm<128, false><<<cdiv(N_NODES, 64), 256>>>(W2, b2);

    // mean pool + fused MLP head
    k_pool<<<cdiv(N_NODES, 256), 128>>>(batch);
    k_mlp <<<N_GRAPHS, HID>>>(Wm1, bm1, Wm2, bm2, out);
}

// round 5
// speedup vs baseline: 1.6865x; 1.3255x over previous
#include <cuda_runtime.h>
#include <math.h>

#define N_NODES 50000
#define N_EDGES 800000
#define IN_C    64
#define HID     128
#define OUT_C   2
#define N_GRAPHS 64

// ---------------- scratch ----------------
__device__ __align__(16) int   g_cnt_e [N_NODES];
__device__ float g_dinv  [N_NODES];
__device__ int   g_off   [N_NODES + 1];
__device__ int   g_cursor[N_NODES];
__device__ int   g_csr   [N_EDGES];
__device__ float g_h     [N_NODES * HID];
__device__ float g_pool  [N_GRAPHS * HID];
__device__ float g_gcnt  [N_GRAPHS];

// ---------------- zero ----------------
__global__ void k_zero() {
    int i = blockIdx.x * blockDim.x + threadIdx.x;
    if (i < N_NODES) g_cnt_e[i] = 0;
    if (i < N_GRAPHS * HID) g_pool[i] = 0.f;
    if (i < N_GRAPHS) g_gcnt[i] = 0.f;
}

// ---------------- degree (4 edges/thread for MLP) ----------------
__global__ void k_deg4(const int* __restrict__ dst) {
    int i4 = blockIdx.x * blockDim.x + threadIdx.x;
    if (i4 >= N_EDGES / 4) return;
    int4 d = ((const int4*)dst)[i4];
    atomicAdd(&g_cnt_e[d.x], 1);
    atomicAdd(&g_cnt_e[d.y], 1);
    atomicAdd(&g_cnt_e[d.z], 1);
    atomicAdd(&g_cnt_e[d.w], 1);
}

// ---------------- single-block exclusive scan, 4 elems/thread ----------------
__global__ void __launch_bounds__(1024) k_scan() {
    __shared__ int wsum[32];
    __shared__ int s_carry;
    int t = threadIdx.x, lane = t & 31, w = t >> 5;
    if (t == 0) s_carry = 0;
    __syncthreads();
    for (int base = 0; base < N_NODES; base += 4096) {
        int i = base + t * 4;
        int4 v = make_int4(0, 0, 0, 0);
        if (i < N_NODES) v = *(const int4*)&g_cnt_e[i];
        int s = v.x + v.y + v.z + v.w;
        int x = s;
        #pragma unroll
        for (int d = 1; d < 32; d <<= 1) {
            int y = __shfl_up_sync(0xffffffffu, x, d);
            if (lane >= d) x += y;
        }
        if (lane == 31) wsum[w] = x;
        __syncthreads();
        if (w == 0) {
            int y = wsum[lane];
            #pragma unroll
            for (int d = 1; d < 32; d <<= 1) {
                int z = __shfl_up_sync(0xffffffffu, y, d);
                if (lane >= d) y += z;
            }
            wsum[lane] = y;
        }
        __syncthreads();
        int excl = s_carry + (w ? wsum[w - 1] : 0) + x - s;
        if (i < N_NODES) {   // N_NODES % 4 == 0 -> whole int4 valid
            int o0 = excl, o1 = o0 + v.x, o2 = o1 + v.y, o3 = o2 + v.z;
            g_off[i]   = o0; g_off[i+1]   = o1; g_off[i+2]   = o2; g_off[i+3]   = o3;
            g_cursor[i]= o0; g_cursor[i+1]= o1; g_cursor[i+2]= o2; g_cursor[i+3]= o3;
            g_dinv[i]   = rsqrtf((float)v.x + 1.0f);
            g_dinv[i+1] = rsqrtf((float)v.y + 1.0f);
            g_dinv[i+2] = rsqrtf((float)v.z + 1.0f);
            g_dinv[i+3] = rsqrtf((float)v.w + 1.0f);
        }
        __syncthreads();
        if (t == 0) s_carry += wsum[31];
        __syncthreads();
    }
    if (t == 0) g_off[N_NODES] = N_EDGES;
}

// ---------------- CSR build (4 edges/thread) ----------------
__global__ void k_csr4(const int* __restrict__ src, const int* __restrict__ dst) {
    int i4 = blockIdx.x * blockDim.x + threadIdx.x;
    if (i4 >= N_EDGES / 4) return;
    int4 s = ((const int4*)src)[i4];
    int4 d = ((const int4*)dst)[i4];
    int p0 = atomicAdd(&g_cursor[d.x], 1);
    int p1 = atomicAdd(&g_cursor[d.y], 1);
    int p2 = atomicAdd(&g_cursor[d.z], 1);
    int p3 = atomicAdd(&g_cursor[d.w], 1);
    g_csr[p0] = s.x; g_csr[p1] = s.y; g_csr[p2] = s.z; g_csr[p3] = s.w;
}

// ---------------- fused layer 1: agg(x, 64 feats) + GEMM(K=64) + relu -> g_h
// block = 64 nodes x 128 cols, 256 threads. smem: sA 16KB + sW 32KB = 48KB.
__global__ void __launch_bounds__(256) k_fused1(const float4* __restrict__ X,
                                                const float4* __restrict__ W4,
                                                const float4* __restrict__ b4) {
    __shared__ __align__(16) float4 sA[64 * 16];   // [node][c], 64 feats
    __shared__ __align__(16) float4 sW[64 * 32];   // [k][col/4]
    int t = threadIdx.x, lane = t & 31, w = t >> 5;
    int row0 = blockIdx.x * 64;

    // load full W (64x128)
    for (int i = t; i < 64 * 32; i += 256) sW[i] = W4[i];

    // aggregation: warp per node, lanes 0-15/16-31 interleave edges
    int c = lane & 15, half = lane >> 4;
    #pragma unroll 1
    for (int it = 0; it < 8; it++) {
        int n = row0 + it * 8 + w;
        if (n < N_NODES) {
            float dn = g_dinv[n];
            float4 acc = make_float4(0.f, 0.f, 0.f, 0.f);
            if (half == 0) {
                float4 v = X[(size_t)n * 16 + c];
                acc.x = dn * v.x; acc.y = dn * v.y; acc.z = dn * v.z; acc.w = dn * v.w;
            }
            int e0 = g_off[n] + half, e1 = g_off[n + 1];
            for (int e = e0; e < e1; e += 2) {
                int s = g_csr[e];
                float ds = g_dinv[s];
                float4 v = X[(size_t)s * 16 + c];
                acc.x += ds * v.x; acc.y += ds * v.y; acc.z += ds * v.z; acc.w += ds * v.w;
            }
            acc.x += __shfl_xor_sync(0xffffffffu, acc.x, 16);
            acc.y += __shfl_xor_sync(0xffffffffu, acc.y, 16);
            acc.z += __shfl_xor_sync(0xffffffffu, acc.z, 16);
            acc.w += __shfl_xor_sync(0xffffffffu, acc.w, 16);
            if (half == 0) {
                acc.x *= dn; acc.y *= dn; acc.z *= dn; acc.w *= dn;
                sA[(it * 8 + w) * 16 + c] = acc;
            }
        } else if (half == 0) {
            sA[(it * 8 + w) * 16 + c] = make_float4(0.f, 0.f, 0.f, 0.f);
        }
    }
    __syncthreads();

    // GEMM: 8 rows x 4 cols per thread
    int tx = t & 31, ty = t >> 5;
    float acc[8][4];
    #pragma unroll
    for (int rr = 0; rr < 8; rr++)
        #pragma unroll
        for (int cc = 0; cc < 4; cc++) acc[rr][cc] = 0.f;

    #pragma unroll
    for (int k4 = 0; k4 < 16; k4++) {
        float4 w0 = sW[(k4 * 4 + 0) * 32 + tx];
        float4 w1 = sW[(k4 * 4 + 1) * 32 + tx];
        float4 w2 = sW[(k4 * 4 + 2) * 32 + tx];
        float4 w3 = sW[(k4 * 4 + 3) * 32 + tx];
        #pragma unroll
        for (int rr = 0; rr < 8; rr++) {
            float4 a = sA[(ty + rr * 8) * 16 + k4];
            acc[rr][0] += a.x * w0.x + a.y * w1.x + a.z * w2.x + a.w * w3.x;
            acc[rr][1] += a.x * w0.y + a.y * w1.y + a.z * w2.y + a.w * w3.y;
            acc[rr][2] += a.x * w0.z + a.y * w1.z + a.z * w2.z + a.w * w3.z;
            acc[rr][3] += a.x * w0.w + a.y * w1.w + a.z * w2.w + a.w * w3.w;
        }
    }

    float4 bb = b4[tx];
    #pragma unroll
    for (int rr = 0; rr < 8; rr++) {
        int gr = row0 + ty + rr * 8;
        if (gr < N_NODES) {
            float4 o;
            o.x = fmaxf(acc[rr][0] + bb.x, 0.f);
            o.y = fmaxf(acc[rr][1] + bb.y, 0.f);
            o.z = fmaxf(acc[rr][2] + bb.z, 0.f);
            o.w = fmaxf(acc[rr][3] + bb.w, 0.f);
            ((float4*)g_h)[(size_t)gr * 32 + tx] = o;
        }
    }
}

// ---------------- fused layer 2: agg(g_h,128) + GEMM(K=128) + mean-pool ------
// smem: sA 64x32 float4 (32KB) + sW 32x32 float4 (16KB) = 48KB.
__global__ void __launch_bounds__(256) k_fused2(const float4* __restrict__ W4,
                                                const float4* __restrict__ b4,
                                                const int* __restrict__ batch) {
    __shared__ __align__(16) float4 sA[64 * 32];
    __shared__ __align__(16) float4 sW[32 * 32];
    int t = threadIdx.x, lane = t & 31, w = t >> 5;
    int row0 = blockIdx.x * 64;
    const float4* H = (const float4*)g_h;

    // aggregation: warp per node, lane = float4 chunk (128 feats)
    #pragma unroll 1
    for (int it = 0; it < 8; it++) {
        int n = row0 + it * 8 + w;
        if (n < N_NODES) {
            float dn = g_dinv[n];
            float4 v = H[(size_t)n * 32 + lane];
            float4 acc;
            acc.x = dn * v.x; acc.y = dn * v.y; acc.z = dn * v.z; acc.w = dn * v.w;
            int e0 = g_off[n], e1 = g_off[n + 1];
            int e = e0;
            for (; e + 1 < e1; e += 2) {
                int s0 = g_csr[e], s1 = g_csr[e + 1];
                float d0 = g_dinv[s0], d1 = g_dinv[s1];
                float4 v0 = H[(size_t)s0 * 32 + lane];
                float4 v1 = H[(size_t)s1 * 32 + lane];
                acc.x += d0 * v0.x + d1 * v1.x;
                acc.y += d0 * v0.y + d1 * v1.y;
                acc.z += d0 * v0.z + d1 * v1.z;
                acc.w += d0 * v0.w + d1 * v1.w;
            }
            if (e < e1) {
                int s0 = g_csr[e];
                float d0 = g_dinv[s0];
                float4 v0 = H[(size_t)s0 * 32 + lane];
                acc.x += d0 * v0.x; acc.y += d0 * v0.y; acc.z += d0 * v0.z; acc.w += d0 * v0.w;
            }
            acc.x *= dn; acc.y *= dn; acc.z *= dn; acc.w *= dn;
            sA[(it * 8 + w) * 32 + lane] = acc;
        } else {
            sA[(it * 8 + w) * 32 + lane] = make_float4(0.f, 0.f, 0.f, 0.f);
        }
    }

    // GEMM K=128, kt tiles of 32
    int tx = t & 31, ty = t >> 5;
    float acc[8][4];
    #pragma unroll
    for (int rr = 0; rr < 8; rr++)
        #pragma unroll
        for (int cc = 0; cc < 4; cc++) acc[rr][cc] = 0.f;

    for (int kt = 0; kt < 128; kt += 32) {
        __syncthreads();
        for (int i = t; i < 32 * 32; i += 256) sW[i] = W4[kt * 32 + i];
        __syncthreads();
        #pragma unroll
        for (int k4 = 0; k4 < 8; k4++) {
            float4 w0 = sW[(k4 * 4 + 0) * 32 + tx];
            float4 w1 = sW[(k4 * 4 + 1) * 32 + tx];
            float4 w2 = sW[(k4 * 4 + 2) * 32 + tx];
            float4 w3 = sW[(k4 * 4 + 3) * 32 + tx];
            #pragma unroll
            for (int rr = 0; rr < 8; rr++) {
                float4 a = sA[(ty + rr * 8) * 32 + (kt >> 2) + k4];
                acc[rr][0] += a.x * w0.x + a.y * w1.x + a.z * w2.x + a.w * w3.x;
                acc[rr][1] += a.x * w0.y + a.y * w1.y + a.z * w2.y + a.w * w3.y;
                acc[rr][2] += a.x * w0.z + a.y * w1.z + a.z * w2.z + a.w * w3.z;
                acc[rr][3] += a.x * w0.w + a.y * w1.w + a.z * w2.w + a.w * w3.w;
            }
        }
    }
    __syncthreads();

    // stage outputs back into sA, then run-length mean-pool into g_pool
    float4 bb = b4[tx];
    #pragma unroll
    for (int rr = 0; rr < 8; rr++) {
        float4 o;
        o.x = acc[rr][0] + bb.x;
        o.y = acc[rr][1] + bb.y;
        o.z = acc[rr][2] + bb.z;
        o.w = acc[rr][3] + bb.w;
        sA[(ty + rr * 8) * 32 + tx] = o;
    }
    __syncthreads();

    const float* sAf = (const float*)sA;
    int j = t & 127, half = t >> 7;
    int rbeg = half * 32;
    int rend = min(rbeg + 32, N_NODES - row0);
    float pacc = 0.f;
    int cur = -1, cnt = 0;
    for (int r = rbeg; r < rend; r++) {
        int b = __ldg(&batch[row0 + r]);
        if (b != cur) {
            if (cur >= 0) {
                atomicAdd(&g_pool[cur * HID + j], pacc);
                if (j == 0) atomicAdd(&g_gcnt[cur], (float)cnt);
            }
            cur = b; pacc = 0.f; cnt = 0;
        }
        pacc += sAf[r * 128 + j];
        cnt++;
    }
    if (cur >= 0) {
        atomicAdd(&g_pool[cur * HID + j], pacc);
        if (j == 0) atomicAdd(&g_gcnt[cur], (float)cnt);
    }
}

// ---------------- fused MLP head ----------------
__global__ void __launch_bounds__(128) k_mlp(const float* __restrict__ Wm1,
                                             const float* __restrict__ bm1,
                                             const float* __restrict__ Wm2,
                                             const float* __restrict__ bm2,
                                             float* __restrict__ out) {
    __shared__ float grow[HID];
    __shared__ float r0[HID], r1[HID];
    int r = blockIdx.x;
    int j = threadIdx.x;
    grow[j] = g_pool[r * HID + j] / fmaxf(g_gcnt[r], 1.0f);
    __syncthreads();
    float acc = bm1[j];
    #pragma unroll 8
    for (int k = 0; k < HID; k++) acc += grow[k] * Wm1[k * HID + j];
    float h = fmaxf(acc, 0.f);
    r0[j] = h * Wm2[j * OUT_C + 0];
    r1[j] = h * Wm2[j * OUT_C + 1];
    __syncthreads();
    #pragma unroll
    for (int s = 64; s > 0; s >>= 1) {
        if (j < s) { r0[j] += r0[j + s]; r1[j] += r1[j + s]; }
        __syncthreads();
    }
    if (j == 0) {
        out[r * OUT_C + 0] = r0[0] + bm2[0];
        out[r * OUT_C + 1] = r1[0] + bm2[1];
    }
}

// ---------------- launch ----------------
static inline int cdiv(int a, int b) { return (a + b - 1) / b; }

extern "C" void kernel_launch(void* const* d_in, const int* in_sizes, int n_in,
                              void* d_out, int out_size) {
    const float* x    = (const float*)d_in[0];
    const int*   ei   = (const int*)d_in[1];
    const int*   src  = ei;
    const int*   dst  = ei + N_EDGES;
    const int*   batch= (const int*)d_in[2];
    const float* W1  = (const float*)d_in[3];
    const float* b1  = (const float*)d_in[4];
    const float* W2  = (const float*)d_in[5];
    const float* b2  = (const float*)d_in[6];
    const float* Wm1 = (const float*)d_in[7];
    const float* bm1 = (const float*)d_in[8];
    const float* Wm2 = (const float*)d_in[9];
    const float* bm2 = (const float*)d_in[10];
    float* out = (float*)d_out;

    const int T = 256;

    k_zero<<<cdiv(N_NODES, T), T>>>();
    k_deg4<<<cdiv(N_EDGES / 4, T), T>>>(dst);
    k_scan<<<1, 1024>>>();
    k_csr4<<<cdiv(N_EDGES / 4, T), T>>>(src, dst);

    k_fused1<<<cdiv(N_NODES, 64), 256>>>((const float4*)x, (const float4*)W1,
                                         (const float4*)b1);
    k_fused2<<<cdiv(N_NODES, 64), 256>>>((const float4*)W2, (const float4*)b2, batch);

    k_mlp<<<N_GRAPHS, HID>>>(Wm1, bm1, Wm2, bm2, out);
}